// round 1
// baseline (speedup 1.0000x reference)
#include <cuda_runtime.h>
#include <math.h>

#define BB 8
#define SS 1024
#define DD 1024
#define HH 16
#define DEPTH 64
#define NROWS (BB*SS)

// ---------------- scratch (device globals: allocation-free rule) ----------------
__device__ float g_qh[(size_t)BB*HH*SS*DEPTH];
__device__ float g_kh[(size_t)BB*HH*SS*DEPTH];
__device__ float g_vh[(size_t)BB*HH*SS*DEPTH];
__device__ float g_ctx[(size_t)NROWS*DD];

// ---------------- packed f32x2 helpers (Blackwell FFMA2 path) ----------------
typedef unsigned long long ull;
__device__ __forceinline__ ull pack2(float lo, float hi){
    ull r; asm("mov.b64 %0, {%1, %2};" : "=l"(r) : "f"(lo), "f"(hi)); return r;
}
__device__ __forceinline__ void unpack2(ull v, float& lo, float& hi){
    asm("mov.b64 {%0, %1}, %2;" : "=f"(lo), "=f"(hi) : "l"(v));
}
__device__ __forceinline__ void ffma2(ull& c, ull a, ull b){
    asm("fma.rn.f32x2 %0, %1, %2, %0;" : "+l"(c) : "l"(a), "l"(b));
}

// ---------------- fused projection GEMM: relu(X@W+b) then optional BN ----------------
// C tile 128x128, BK=16, 256 threads, 8x8 per thread via f32x2 pairs.
// Thread owns striped columns col0 + tx + 16*n (n=0..7)  -> conflict-free LDS.
// If WITH_BN: output written in split-head layout [B,H,S,DEPTH]; else plain [r,D].
template<bool WITH_BN>
__global__ __launch_bounds__(256, 2)
void proj_kernel(const float* __restrict__ X, const float* __restrict__ W,
                 const float* __restrict__ bias,
                 const float* __restrict__ gg, const float* __restrict__ be,
                 const float* __restrict__ mm, const float* __restrict__ mv,
                 float* __restrict__ out)
{
    __shared__ float As[16][128];   // As[k][m]
    __shared__ float Bs[16][128];   // Bs[k][n]
    const int tid  = threadIdx.x;
    const int row0 = blockIdx.y * 128;
    const int col0 = blockIdx.x * 128;
    const int tx = tid & 15, ty = tid >> 4;
    const int trow = ty * 8;

    ull acc[8][4];
    #pragma unroll
    for (int m = 0; m < 8; m++)
        #pragma unroll
        for (int n = 0; n < 4; n++) acc[m][n] = 0ull;   // (0.f, 0.f)

    for (int k0 = 0; k0 < DD; k0 += 16) {
        // load A tile 128x16 (transposed into As[k][m])
        #pragma unroll
        for (int i = 0; i < 2; i++) {
            int idx = tid * 2 + i;              // 0..511 float4s
            int r = idx >> 2, kk = (idx & 3) << 2;
            const float4 v = *(const float4*)(X + (size_t)(row0 + r) * DD + (k0 + kk));
            As[kk+0][r] = v.x; As[kk+1][r] = v.y; As[kk+2][r] = v.z; As[kk+3][r] = v.w;
        }
        // load B tile 16x128
        #pragma unroll
        for (int i = 0; i < 2; i++) {
            int idx = tid * 2 + i;
            int kk = idx >> 5, nn = (idx & 31) << 2;
            *(float4*)&Bs[kk][nn] = *(const float4*)(W + (size_t)(k0 + kk) * DD + (col0 + nn));
        }
        __syncthreads();
        #pragma unroll
        for (int kk = 0; kk < 16; kk++) {
            float a[8];
            #pragma unroll
            for (int m = 0; m < 8; m++) a[m] = As[kk][trow + m];
            ull bpk[4];
            #pragma unroll
            for (int n2 = 0; n2 < 4; n2++)
                bpk[n2] = pack2(Bs[kk][tx + 32*n2], Bs[kk][tx + 32*n2 + 16]);
            #pragma unroll
            for (int m = 0; m < 8; m++) {
                ull am = pack2(a[m], a[m]);
                #pragma unroll
                for (int n2 = 0; n2 < 4; n2++) ffma2(acc[m][n2], am, bpk[n2]);
            }
        }
        __syncthreads();
    }

    // epilogue: bias + relu (+ BN), write out
    #pragma unroll
    for (int n2 = 0; n2 < 4; n2++) {
        const int colA = col0 + tx + 32*n2;
        const int colB = colA + 16;
        const float biaA = bias[colA], biaB = bias[colB];
        float scA = 1.f, shA = 0.f, scB = 1.f, shB = 0.f;
        if (WITH_BN) {
            scA = gg[colA] * rsqrtf(mv[colA] + 1e-3f);  shA = be[colA] - mm[colA] * scA;
            scB = gg[colB] * rsqrtf(mv[colB] + 1e-3f);  shB = be[colB] - mm[colB] * scB;
        }
        const int hA = colA >> 6, dA = colA & 63;
        const int hB = colB >> 6, dB = colB & 63;
        #pragma unroll
        for (int m = 0; m < 8; m++) {
            const int r = row0 + trow + m;
            float lo, hi; unpack2(acc[m][n2], lo, hi);
            lo = fmaxf(lo + biaA, 0.f);
            hi = fmaxf(hi + biaB, 0.f);
            if (WITH_BN) {
                lo = lo * scA + shA;
                hi = hi * scB + shB;
                const int bi = r >> 10, si = r & 1023;
                out[(((size_t)bi * HH + hA) * SS + si) * DEPTH + dA] = lo;
                out[(((size_t)bi * HH + hB) * SS + si) * DEPTH + dB] = hi;
            } else {
                out[(size_t)r * DD + colA] = lo;
                out[(size_t)r * DD + colB] = hi;
            }
        }
    }
}

// ---------------- fused attention: scores -> masked softmax -> attn write -> ctx ----------------
#define QT 32
#define SC_STRIDE 1025     // odd stride: rows land on distinct banks
#define QS_STRIDE 68
#define KVT_STRIDE 129
#define VV_STRIDE 72
#define ATT_THREADS 256

__global__ __launch_bounds__(ATT_THREADS, 1)
void attn_kernel(const float* __restrict__ mask, float* __restrict__ attnOut)
{
    extern __shared__ float smbuf[];
    float* sc   = smbuf;                          // QT * SC_STRIDE      (scores, then attn)
    float* qs   = sc + QT * SC_STRIDE;            // QT * QS_STRIDE      (q tile)
    float* mrow = qs + QT * QS_STRIDE;            // SS                  (mask * -1e9)
    float* kv   = mrow + SS;                      // 128*VV_STRIDE       (k-chunk T / v-chunk)

    const int tid = threadIdx.x;
    const int qt0 = blockIdx.x * QT;
    const int h = blockIdx.y, b = blockIdx.z;
    const size_t bh = (size_t)b * HH + h;
    const float* qh = g_qh + bh * SS * DEPTH;
    const float* kh = g_kh + bh * SS * DEPTH;
    const float* vh = g_vh + bh * SS * DEPTH;

    // load q tile + premultiplied mask row
    for (int i4 = tid; i4 < QT * DEPTH / 4; i4 += ATT_THREADS) {
        int r = i4 >> 4, d4 = (i4 & 15) << 2;
        *(float4*)&qs[r * QS_STRIDE + d4] =
            *(const float4*)&qh[(size_t)(qt0 + r) * DEPTH + d4];
    }
    for (int i4 = tid; i4 < SS / 4; i4 += ATT_THREADS) {
        float4 v = *(const float4*)&mask[(size_t)b * SS + i4 * 4];
        v.x *= -1e9f; v.y *= -1e9f; v.z *= -1e9f; v.w *= -1e9f;
        *(float4*)&mrow[i4 * 4] = v;
    }
    __syncthreads();

    const int tx = tid & 15, ty = tid >> 4;
    const int r0 = ty * 2;   // two q rows per thread

    // ---- Phase 1: scores[32][1024] = (qs @ khT) * 0.125 + mask ----
    for (int jc = 0; jc < SS / 128; jc++) {
        const int j0 = jc * 128;
        // load 128 k-rows transposed: kv[k*KVT_STRIDE + j]
        for (int i4 = tid; i4 < 128 * DEPTH / 4; i4 += ATT_THREADS) {
            int j = i4 >> 4, k4 = (i4 & 15) << 2;
            float4 v = *(const float4*)&kh[(size_t)(j0 + j) * DEPTH + k4];
            kv[(k4+0) * KVT_STRIDE + j] = v.x;
            kv[(k4+1) * KVT_STRIDE + j] = v.y;
            kv[(k4+2) * KVT_STRIDE + j] = v.z;
            kv[(k4+3) * KVT_STRIDE + j] = v.w;
        }
        __syncthreads();

        float accA[8] = {0,0,0,0,0,0,0,0};
        float accB[8] = {0,0,0,0,0,0,0,0};
        #pragma unroll 4
        for (int k = 0; k < DEPTH; k++) {
            const float a0 = qs[r0 * QS_STRIDE + k];
            const float a1 = qs[(r0 + 1) * QS_STRIDE + k];
            const float* kp = &kv[k * KVT_STRIDE + tx];
            #pragma unroll
            for (int n = 0; n < 8; n++) {
                const float bv = kp[16 * n];
                accA[n] = fmaf(a0, bv, accA[n]);
                accB[n] = fmaf(a1, bv, accB[n]);
            }
        }
        #pragma unroll
        for (int n = 0; n < 8; n++) {
            const int j = j0 + tx + 16 * n;
            const float mval = mrow[j];
            sc[r0 * SC_STRIDE + j]       = fmaf(accA[n], 0.125f, mval);
            sc[(r0 + 1) * SC_STRIDE + j] = fmaf(accB[n], 0.125f, mval);
        }
        __syncthreads();
    }

    // ---- Phase 2: softmax per row, write attn to GMEM, keep normalized in smem ----
    {
        const int warp = tid >> 5, lane = tid & 31;
        for (int rr = 0; rr < 4; rr++) {
            const int r = warp * 4 + rr;
            float* row = sc + r * SC_STRIDE;
            float mx = -3.4e38f;
            for (int j = lane; j < SS; j += 32) mx = fmaxf(mx, row[j]);
            #pragma unroll
            for (int o = 16; o > 0; o >>= 1) mx = fmaxf(mx, __shfl_xor_sync(0xffffffffu, mx, o));
            float sum = 0.f;
            for (int j = lane; j < SS; j += 32) {
                float e = __expf(row[j] - mx);
                row[j] = e; sum += e;
            }
            #pragma unroll
            for (int o = 16; o > 0; o >>= 1) sum += __shfl_xor_sync(0xffffffffu, sum, o);
            const float inv = 1.f / sum;
            float* gout = attnOut + (bh * SS + (qt0 + r)) * SS;
            for (int j = lane; j < SS; j += 32) {
                float a = row[j] * inv;
                row[j] = a;
                gout[j] = a;
            }
        }
    }
    __syncthreads();

    // ---- Phase 3: ctx[32][64] = attn @ vh ----
    float ct0[4] = {0,0,0,0};
    float ct1[4] = {0,0,0,0};
    for (int jc = 0; jc < SS / 128; jc++) {
        const int j0 = jc * 128;
        for (int i4 = tid; i4 < 128 * DEPTH / 4; i4 += ATT_THREADS) {
            int j = i4 >> 4, d4 = (i4 & 15) << 2;
            *(float4*)&kv[j * VV_STRIDE + d4] =
                *(const float4*)&vh[(size_t)(j0 + j) * DEPTH + d4];
        }
        __syncthreads();
        #pragma unroll 4
        for (int j = 0; j < 128; j++) {
            const float a0 = sc[r0 * SC_STRIDE + j0 + j];
            const float a1 = sc[(r0 + 1) * SC_STRIDE + j0 + j];
            const float* vp = &kv[j * VV_STRIDE + tx];
            #pragma unroll
            for (int n = 0; n < 4; n++) {
                const float bv = vp[16 * n];
                ct0[n] = fmaf(a0, bv, ct0[n]);
                ct1[n] = fmaf(a1, bv, ct1[n]);
            }
        }
        __syncthreads();
    }
    {
        const size_t base0 = ((size_t)b * SS + qt0 + r0) * DD + (size_t)h * DEPTH;
        const size_t base1 = base0 + DD;
        #pragma unroll
        for (int n = 0; n < 4; n++) {
            g_ctx[base0 + tx + 16 * n] = ct0[n];
            g_ctx[base1 + tx + 16 * n] = ct1[n];
        }
    }
}

// ---------------- launch ----------------
extern "C" void kernel_launch(void* const* d_in, const int* in_sizes, int n_in,
                              void* d_out, int out_size)
{
    const float* q    = (const float*)d_in[0];
    const float* k    = (const float*)d_in[1];
    const float* v    = (const float*)d_in[2];
    const float* mask = (const float*)d_in[3];
    const float* wq = (const float*)d_in[4];   const float* bq = (const float*)d_in[5];
    const float* wk = (const float*)d_in[6];   const float* bk = (const float*)d_in[7];
    const float* wv = (const float*)d_in[8];   const float* bv = (const float*)d_in[9];
    const float* wo = (const float*)d_in[10];  const float* bo = (const float*)d_in[11];
    const float* g1 = (const float*)d_in[12];  const float* be1 = (const float*)d_in[13];
    const float* mm1= (const float*)d_in[14];  const float* mv1 = (const float*)d_in[15];
    const float* g2 = (const float*)d_in[16];  const float* be2 = (const float*)d_in[17];
    const float* mm2= (const float*)d_in[18];  const float* mv2 = (const float*)d_in[19];
    const float* g3 = (const float*)d_in[20];  const float* be3 = (const float*)d_in[21];
    const float* mm3= (const float*)d_in[22];  const float* mv3 = (const float*)d_in[23];

    float* out = (float*)d_out;                         // [B,S,D] first (tuple order)
    float* attnOut = out + (size_t)NROWS * DD;          // then [B,H,S,S]

    float *qh_p = nullptr, *kh_p = nullptr, *vh_p = nullptr, *ctx_p = nullptr;
    cudaGetSymbolAddress((void**)&qh_p,  g_qh);
    cudaGetSymbolAddress((void**)&kh_p,  g_kh);
    cudaGetSymbolAddress((void**)&vh_p,  g_vh);
    cudaGetSymbolAddress((void**)&ctx_p, g_ctx);

    dim3 pgrid(DD / 128, NROWS / 128);
    proj_kernel<true><<<pgrid, 256>>>(q, wq, bq, g1, be1, mm1, mv1, qh_p);
    proj_kernel<true><<<pgrid, 256>>>(k, wk, bk, g2, be2, mm2, mv2, kh_p);
    proj_kernel<true><<<pgrid, 256>>>(v, wv, bv, g3, be3, mm3, mv3, vh_p);

    const size_t smem = (size_t)(QT * SC_STRIDE + QT * QS_STRIDE + SS + 128 * VV_STRIDE)
                        * sizeof(float);   // 180,864 B
    cudaFuncSetAttribute(attn_kernel, cudaFuncAttributeMaxDynamicSharedMemorySize, (int)smem);
    dim3 agrid(SS / QT, HH, BB);
    attn_kernel<<<agrid, ATT_THREADS, smem>>>(mask, attnOut);

    proj_kernel<false><<<pgrid, 256>>>(ctx_p, wo, bo, nullptr, nullptr, nullptr, nullptr, out);
}

// round 6
// speedup vs baseline: 1.4991x; 1.4991x over previous
#include <cuda_runtime.h>
#include <cuda_bf16.h>
#include <cstdint>
#include <math.h>

#define BB 8
#define SS 1024
#define DD 1024
#define HH 16
#define DEPTH 64
#define NROWS (BB*SS)

// ================= scratch (device globals: allocation-free rule) =================
__device__ float g_qh[(size_t)BB*HH*SS*DEPTH];
__device__ float g_kh[(size_t)BB*HH*SS*DEPTH];
__device__ float g_vh[(size_t)BB*HH*SS*DEPTH];
__device__ float g_ctx[(size_t)NROWS*DD];

__device__ __nv_bfloat16 g_qs_h[(size_t)NROWS*DD], g_qs_l[(size_t)NROWS*DD];
__device__ __nv_bfloat16 g_ks_h[(size_t)NROWS*DD], g_ks_l[(size_t)NROWS*DD];
__device__ __nv_bfloat16 g_vs_h[(size_t)NROWS*DD], g_vs_l[(size_t)NROWS*DD];
__device__ __nv_bfloat16 g_cs_h[(size_t)NROWS*DD], g_cs_l[(size_t)NROWS*DD];
__device__ __nv_bfloat16 g_wqt_h[(size_t)DD*DD], g_wqt_l[(size_t)DD*DD];
__device__ __nv_bfloat16 g_wkt_h[(size_t)DD*DD], g_wkt_l[(size_t)DD*DD];
__device__ __nv_bfloat16 g_wvt_h[(size_t)DD*DD], g_wvt_l[(size_t)DD*DD];
__device__ __nv_bfloat16 g_wot_h[(size_t)DD*DD], g_wot_l[(size_t)DD*DD];

// ================= warp-MMA helpers (PTX-portable: sm_80+ features only) =================
__device__ __forceinline__ uint32_t smem_u32(const void* p){
    uint32_t a;
    asm("{ .reg .u64 t; cvta.to.shared.u64 t, %1; cvt.u32.u64 %0, t; }" : "=r"(a) : "l"(p));
    return a;
}
__device__ __forceinline__ void ldm4(uint32_t* r, uint32_t addr){
    asm volatile("ldmatrix.sync.aligned.m8n8.x4.shared.b16 {%0,%1,%2,%3}, [%4];"
        : "=r"(r[0]), "=r"(r[1]), "=r"(r[2]), "=r"(r[3]) : "r"(addr));
}
__device__ __forceinline__ void mma_bf16(float* d, const uint32_t* a, const uint32_t* b){
    asm volatile("mma.sync.aligned.m16n8k16.row.col.f32.bf16.bf16.f32 "
        "{%0,%1,%2,%3}, {%4,%5,%6,%7}, {%8,%9}, {%0,%1,%2,%3};"
        : "+f"(d[0]), "+f"(d[1]), "+f"(d[2]), "+f"(d[3])
        : "r"(a[0]), "r"(a[1]), "r"(a[2]), "r"(a[3]), "r"(b[0]), "r"(b[1]));
}
__device__ __forceinline__ void cp16(uint32_t saddr, const void* g){
    asm volatile("cp.async.cg.shared.global [%0], [%1], 16;" :: "r"(saddr), "l"(g));
}

// ================= split: fp32 -> (bf16 hi, bf16 lo) =================
__global__ void split_kernel(const float* __restrict__ x,
                             __nv_bfloat16* __restrict__ hi, __nv_bfloat16* __restrict__ lo, int n4)
{
    int i = blockIdx.x * blockDim.x + threadIdx.x;
    if (i >= n4) return;
    float4 v = *(const float4*)(x + (size_t)i * 4);
    __nv_bfloat16 h0 = __float2bfloat16(v.x), h1 = __float2bfloat16(v.y);
    __nv_bfloat16 h2 = __float2bfloat16(v.z), h3 = __float2bfloat16(v.w);
    __nv_bfloat16 l0 = __float2bfloat16(v.x - __bfloat162float(h0));
    __nv_bfloat16 l1 = __float2bfloat16(v.y - __bfloat162float(h1));
    __nv_bfloat16 l2 = __float2bfloat16(v.z - __bfloat162float(h2));
    __nv_bfloat16 l3 = __float2bfloat16(v.w - __bfloat162float(h3));
    __nv_bfloat162* hp = (__nv_bfloat162*)(hi + (size_t)i * 4);
    __nv_bfloat162* lp = (__nv_bfloat162*)(lo + (size_t)i * 4);
    hp[0] = __nv_bfloat162(h0, h1); hp[1] = __nv_bfloat162(h2, h3);
    lp[0] = __nv_bfloat162(l0, l1); lp[1] = __nv_bfloat162(l2, l3);
}

// ================= transpose + split for weights: W[k][n] -> Wt[n][k] =================
__global__ void tsplit_kernel(const float* __restrict__ W,
                              __nv_bfloat16* __restrict__ th, __nv_bfloat16* __restrict__ tl)
{
    __shared__ float t[32][33];
    const int x0 = blockIdx.x * 32, y0 = blockIdx.y * 32;
    for (int i = threadIdx.y; i < 32; i += 8)
        t[i][threadIdx.x] = W[(size_t)(y0 + i) * DD + x0 + threadIdx.x];
    __syncthreads();
    for (int i = threadIdx.y; i < 32; i += 8) {
        float v = t[threadIdx.x][i];
        __nv_bfloat16 h = __float2bfloat16(v);
        __nv_bfloat16 l = __float2bfloat16(v - __bfloat162float(h));
        size_t o = (size_t)(x0 + i) * DD + y0 + threadIdx.x;
        th[o] = h; tl[o] = l;
    }
}

// ================= bf16x3 GEMM via mma.sync, cp.async double-buffered =================
// C tile 128x128, BK=32, 256 threads = 8 warps (4M x 2N), warp tile 32x64.
#define NC 32
#define BK 32
#define TSTRIDE 40                       // bf16 per smem row (80B, ldmatrix conflict-free)
#define TILE_BYT (128*TSTRIDE*2)         // 10240
#define STAGE_BYT (4*TILE_BYT)           // 40960 (Ah, Al, Bh, Bl)

template<bool WITH_BN>
__global__ __launch_bounds__(256)
void gemm_kernel(const __nv_bfloat16* __restrict__ Ah, const __nv_bfloat16* __restrict__ Al,
                 const __nv_bfloat16* __restrict__ Bh, const __nv_bfloat16* __restrict__ Bl,
                 const float* __restrict__ bias,
                 const float* __restrict__ gg, const float* __restrict__ be,
                 const float* __restrict__ mm, const float* __restrict__ mv,
                 float* __restrict__ out)
{
    extern __shared__ char dsm[];
    __shared__ float s_bias[128], s_scale[128], s_shift[128];

    const int tid = threadIdx.x, lane = tid & 31, wid = tid >> 5;
    const int row0 = blockIdx.y * 128, col0 = blockIdx.x * 128;
    const uint32_t smb = smem_u32(dsm);

    if (tid < 128) {
        int c = col0 + tid;
        s_bias[tid] = bias[c];
        if (WITH_BN) {
            float sc = gg[c] * rsqrtf(mv[c] + 1e-3f);
            s_scale[tid] = sc;
            s_shift[tid] = be[c] - mm[c] * sc;
        }
    }

    const __nv_bfloat16* srcs[4] = {Ah, Al, Bh, Bl};

    auto fill = [&](int c, int bsel) {
        const int k0 = c * BK;
        #pragma unroll
        for (int t = 0; t < 4; t++) {
            const __nv_bfloat16* src = srcs[t];
            const int rbase = (t >= 2) ? col0 : row0;
            #pragma unroll
            for (int i = 0; i < 2; i++) {
                int idx = tid + i * 256;             // 0..511
                int r = idx >> 2, c4 = idx & 3;      // r: 0..127, c4: 0..3
                uint32_t sa = smb + bsel * STAGE_BYT + t * TILE_BYT + (r * TSTRIDE + c4 * 8) * 2;
                cp16(sa, src + (size_t)(rbase + r) * DD + k0 + c4 * 8);
            }
        }
        asm volatile("cp.async.commit_group;");
    };

    // per-thread ldmatrix address components
    const int wm = (wid & 3) * 32, wn = (wid >> 2) * 64;
    const int aRow = wm + (lane & 15);
    const int aK   = (lane >> 4) * 8;
    const int bRow = wn + (lane & 7) + ((lane >> 4) << 3);
    const int bK   = ((lane >> 3) & 1) * 8;

    float acc[2][8][4];
    #pragma unroll
    for (int m = 0; m < 2; m++)
        #pragma unroll
        for (int n = 0; n < 8; n++)
            #pragma unroll
            for (int u = 0; u < 4; u++) acc[m][n][u] = 0.f;

    auto compute = [&](int bsel) {
        const uint32_t stg = smb + bsel * STAGE_BYT;
        #pragma unroll
        for (int kk = 0; kk < BK; kk += 16) {
            uint32_t ahf[2][4], alf[2][4];
            #pragma unroll
            for (int m = 0; m < 2; m++) {
                const uint32_t off = ((aRow + m * 16) * TSTRIDE + kk + aK) * 2;
                ldm4(ahf[m], stg + off);                 // Ah tile
                ldm4(alf[m], stg + TILE_BYT + off);      // Al tile
            }
            #pragma unroll
            for (int g = 0; g < 4; g++) {
                const uint32_t off = ((bRow + g * 16) * TSTRIDE + kk + bK) * 2;
                uint32_t bh2[4], bl2[4];
                ldm4(bh2, stg + 2 * TILE_BYT + off);     // Bh tile (2 n-atoms)
                ldm4(bl2, stg + 3 * TILE_BYT + off);     // Bl tile
                #pragma unroll
                for (int m = 0; m < 2; m++) {
                    mma_bf16(acc[m][2*g],   ahf[m], bh2);
                    mma_bf16(acc[m][2*g],   ahf[m], bl2);
                    mma_bf16(acc[m][2*g],   alf[m], bh2);
                    mma_bf16(acc[m][2*g+1], ahf[m], bh2 + 2);
                    mma_bf16(acc[m][2*g+1], ahf[m], bl2 + 2);
                    mma_bf16(acc[m][2*g+1], alf[m], bh2 + 2);
                }
            }
        }
    };

    fill(0, 0);
    for (int c = 0; c < NC; c++) {
        if (c + 1 < NC) {
            fill(c + 1, (c + 1) & 1);
            asm volatile("cp.async.wait_group 1;" ::: "memory");
        } else {
            asm volatile("cp.async.wait_group 0;" ::: "memory");
        }
        __syncthreads();
        compute(c & 1);
        __syncthreads();
    }

    // epilogue: bias + relu (+BN); acc layout: d0,d1 = (row lane>>2, col (lane&3)*2 +0/1), d2,d3 = row+8
    #pragma unroll
    for (int m = 0; m < 2; m++) {
        #pragma unroll
        for (int h2 = 0; h2 < 2; h2++) {
            const int r = row0 + wm + m * 16 + h2 * 8 + (lane >> 2);
            const int bidx = r >> 10, sidx = r & 1023;
            #pragma unroll
            for (int n = 0; n < 8; n++) {
                const int cl = wn + n * 8 + (lane & 3) * 2;
                float v0 = acc[m][n][h2 ? 2 : 0];
                float v1 = acc[m][n][h2 ? 3 : 1];
                v0 = fmaxf(v0 + s_bias[cl],     0.f);
                v1 = fmaxf(v1 + s_bias[cl + 1], 0.f);
                if (WITH_BN) {
                    v0 = v0 * s_scale[cl]     + s_shift[cl];
                    v1 = v1 * s_scale[cl + 1] + s_shift[cl + 1];
                }
                float2 p; p.x = v0; p.y = v1;
                if (WITH_BN) {
                    const int cg = col0 + cl;
                    const int hh = cg >> 6, d0i = cg & 63;
                    *(float2*)&out[(((size_t)bidx * HH + hh) * SS + sidx) * DEPTH + d0i] = p;
                } else {
                    *(float2*)&out[(size_t)r * DD + col0 + cl] = p;
                }
            }
        }
    }
}

// ================= fused attention (4x4 retile; numerics identical to R0) =================
#define QT 32
#define SC_STRIDE 1025
#define QS_STRIDE 68
#define KVT_STRIDE 129
#define VV_STRIDE 72
#define ATT_THREADS 256

__global__ __launch_bounds__(ATT_THREADS, 1)
void attn_kernel(const float* __restrict__ mask, float* __restrict__ attnOut)
{
    extern __shared__ float smbuf[];
    float* sc   = smbuf;
    float* qs   = sc + QT * SC_STRIDE;
    float* mrow = qs + QT * QS_STRIDE;
    float* kv   = mrow + SS;

    const int tid = threadIdx.x;
    const int qt0 = blockIdx.x * QT;
    const int h = blockIdx.y, b = blockIdx.z;
    const size_t bh = (size_t)b * HH + h;
    const float* qh = g_qh + bh * SS * DEPTH;
    const float* kh = g_kh + bh * SS * DEPTH;
    const float* vh = g_vh + bh * SS * DEPTH;

    for (int i4 = tid; i4 < QT * DEPTH / 4; i4 += ATT_THREADS) {
        int r = i4 >> 4, d4 = (i4 & 15) << 2;
        *(float4*)&qs[r * QS_STRIDE + d4] =
            *(const float4*)&qh[(size_t)(qt0 + r) * DEPTH + d4];
    }
    for (int i4 = tid; i4 < SS / 4; i4 += ATT_THREADS) {
        float4 v = *(const float4*)&mask[(size_t)b * SS + i4 * 4];
        v.x *= -1e9f; v.y *= -1e9f; v.z *= -1e9f; v.w *= -1e9f;
        *(float4*)&mrow[i4 * 4] = v;
    }
    __syncthreads();

    const int tx = tid & 31, ty = tid >> 5;
    const int r0 = ty * 4;

    for (int jc = 0; jc < SS / 128; jc++) {
        const int j0 = jc * 128;
        for (int i4 = tid; i4 < 128 * DEPTH / 4; i4 += ATT_THREADS) {
            int j = i4 >> 4, k4 = (i4 & 15) << 2;
            float4 v = *(const float4*)&kh[(size_t)(j0 + j) * DEPTH + k4];
            kv[(k4+0) * KVT_STRIDE + j] = v.x;
            kv[(k4+1) * KVT_STRIDE + j] = v.y;
            kv[(k4+2) * KVT_STRIDE + j] = v.z;
            kv[(k4+3) * KVT_STRIDE + j] = v.w;
        }
        __syncthreads();

        float acc[4][4];
        #pragma unroll
        for (int rr = 0; rr < 4; rr++)
            #pragma unroll
            for (int n = 0; n < 4; n++) acc[rr][n] = 0.f;

        #pragma unroll 4
        for (int k = 0; k < DEPTH; k++) {
            float a[4];
            #pragma unroll
            for (int rr = 0; rr < 4; rr++) a[rr] = qs[(r0 + rr) * QS_STRIDE + k];
            const float* kp = &kv[k * KVT_STRIDE + tx];
            float bv[4];
            #pragma unroll
            for (int n = 0; n < 4; n++) bv[n] = kp[32 * n];
            #pragma unroll
            for (int rr = 0; rr < 4; rr++)
                #pragma unroll
                for (int n = 0; n < 4; n++)
                    acc[rr][n] = fmaf(a[rr], bv[n], acc[rr][n]);
        }
        #pragma unroll
        for (int n = 0; n < 4; n++) {
            const int j = j0 + tx + 32 * n;
            const float mval = mrow[j];
            #pragma unroll
            for (int rr = 0; rr < 4; rr++)
                sc[(r0 + rr) * SC_STRIDE + j] = fmaf(acc[rr][n], 0.125f, mval);
        }
        __syncthreads();
    }

    {
        const int warp = tid >> 5, lane = tid & 31;
        for (int rr = 0; rr < 4; rr++) {
            const int r = warp * 4 + rr;
            float* row = sc + r * SC_STRIDE;
            float mx = -3.4e38f;
            for (int j = lane; j < SS; j += 32) mx = fmaxf(mx, row[j]);
            #pragma unroll
            for (int o = 16; o > 0; o >>= 1) mx = fmaxf(mx, __shfl_xor_sync(0xffffffffu, mx, o));
            float sum = 0.f;
            for (int j = lane; j < SS; j += 32) {
                float e = __expf(row[j] - mx);
                row[j] = e; sum += e;
            }
            #pragma unroll
            for (int o = 16; o > 0; o >>= 1) sum += __shfl_xor_sync(0xffffffffu, sum, o);
            const float inv = 1.f / sum;
            float* gout = attnOut + (bh * SS + (qt0 + r)) * SS;
            for (int j = lane; j < SS; j += 32) {
                float a = row[j] * inv;
                row[j] = a;
                gout[j] = a;
            }
        }
    }
    __syncthreads();

    float ct[4][2];
    #pragma unroll
    for (int rr = 0; rr < 4; rr++) { ct[rr][0] = 0.f; ct[rr][1] = 0.f; }

    for (int jc = 0; jc < SS / 128; jc++) {
        const int j0 = jc * 128;
        for (int i4 = tid; i4 < 128 * DEPTH / 4; i4 += ATT_THREADS) {
            int j = i4 >> 4, d4 = (i4 & 15) << 2;
            *(float4*)&kv[j * VV_STRIDE + d4] =
                *(const float4*)&vh[(size_t)(j0 + j) * DEPTH + d4];
        }
        __syncthreads();
        #pragma unroll 4
        for (int j = 0; j < 128; j++) {
            float a[4];
            #pragma unroll
            for (int rr = 0; rr < 4; rr++) a[rr] = sc[(r0 + rr) * SC_STRIDE + j0 + j];
            const float* vp = &kv[j * VV_STRIDE + tx];
            const float v0 = vp[0], v1 = vp[32];
            #pragma unroll
            for (int rr = 0; rr < 4; rr++) {
                ct[rr][0] = fmaf(a[rr], v0, ct[rr][0]);
                ct[rr][1] = fmaf(a[rr], v1, ct[rr][1]);
            }
        }
        __syncthreads();
    }
    {
        #pragma unroll
        for (int rr = 0; rr < 4; rr++) {
            const size_t base = ((size_t)b * SS + qt0 + r0 + rr) * DD + (size_t)h * DEPTH;
            g_ctx[base + tx]      = ct[rr][0];
            g_ctx[base + tx + 32] = ct[rr][1];
        }
    }
}

// ================= launch =================
extern "C" void kernel_launch(void* const* d_in, const int* in_sizes, int n_in,
                              void* d_out, int out_size)
{
    const float* q    = (const float*)d_in[0];
    const float* k    = (const float*)d_in[1];
    const float* v    = (const float*)d_in[2];
    const float* mask = (const float*)d_in[3];
    const float* wq = (const float*)d_in[4];   const float* bq = (const float*)d_in[5];
    const float* wk = (const float*)d_in[6];   const float* bk = (const float*)d_in[7];
    const float* wv = (const float*)d_in[8];   const float* bv = (const float*)d_in[9];
    const float* wo = (const float*)d_in[10];  const float* bo = (const float*)d_in[11];
    const float* g1 = (const float*)d_in[12];  const float* be1 = (const float*)d_in[13];
    const float* mm1= (const float*)d_in[14];  const float* mv1 = (const float*)d_in[15];
    const float* g2 = (const float*)d_in[16];  const float* be2 = (const float*)d_in[17];
    const float* mm2= (const float*)d_in[18];  const float* mv2 = (const float*)d_in[19];
    const float* g3 = (const float*)d_in[20];  const float* be3 = (const float*)d_in[21];
    const float* mm3= (const float*)d_in[22];  const float* mv3 = (const float*)d_in[23];

    float* out = (float*)d_out;                   // [B,S,D] first (tuple order)
    float* attnOut = out + (size_t)NROWS * DD;    // then [B,H,S,S]

    float *qh_p, *kh_p, *vh_p, *ctx_p;
    cudaGetSymbolAddress((void**)&qh_p,  g_qh);
    cudaGetSymbolAddress((void**)&kh_p,  g_kh);
    cudaGetSymbolAddress((void**)&vh_p,  g_vh);
    cudaGetSymbolAddress((void**)&ctx_p, g_ctx);
    __nv_bfloat16 *qsh, *qsl, *ksh, *ksl, *vsh, *vsl, *csh, *csl;
    __nv_bfloat16 *wqh, *wql, *wkh, *wkl, *wvh, *wvl, *woh, *wol;
    cudaGetSymbolAddress((void**)&qsh, g_qs_h); cudaGetSymbolAddress((void**)&qsl, g_qs_l);
    cudaGetSymbolAddress((void**)&ksh, g_ks_h); cudaGetSymbolAddress((void**)&ksl, g_ks_l);
    cudaGetSymbolAddress((void**)&vsh, g_vs_h); cudaGetSymbolAddress((void**)&vsl, g_vs_l);
    cudaGetSymbolAddress((void**)&csh, g_cs_h); cudaGetSymbolAddress((void**)&csl, g_cs_l);
    cudaGetSymbolAddress((void**)&wqh, g_wqt_h); cudaGetSymbolAddress((void**)&wql, g_wqt_l);
    cudaGetSymbolAddress((void**)&wkh, g_wkt_h); cudaGetSymbolAddress((void**)&wkl, g_wkt_l);
    cudaGetSymbolAddress((void**)&wvh, g_wvt_h); cudaGetSymbolAddress((void**)&wvl, g_wvt_l);
    cudaGetSymbolAddress((void**)&woh, g_wot_h); cudaGetSymbolAddress((void**)&wol, g_wot_l);

    const int n4 = NROWS * DD / 4;
    split_kernel<<<n4 / 256, 256>>>(q, qsh, qsl, n4);
    split_kernel<<<n4 / 256, 256>>>(k, ksh, ksl, n4);
    split_kernel<<<n4 / 256, 256>>>(v, vsh, vsl, n4);
    dim3 tgrid(DD / 32, DD / 32), tblk(32, 8);
    tsplit_kernel<<<tgrid, tblk>>>(wq, wqh, wql);
    tsplit_kernel<<<tgrid, tblk>>>(wk, wkh, wkl);
    tsplit_kernel<<<tgrid, tblk>>>(wv, wvh, wvl);
    tsplit_kernel<<<tgrid, tblk>>>(wo, woh, wol);

    const int gsmem = 2 * STAGE_BYT;   // 81920
    cudaFuncSetAttribute(gemm_kernel<true>,  cudaFuncAttributeMaxDynamicSharedMemorySize, gsmem);
    cudaFuncSetAttribute(gemm_kernel<false>, cudaFuncAttributeMaxDynamicSharedMemorySize, gsmem);
    dim3 ggrid(DD / 128, NROWS / 128);
    gemm_kernel<true><<<ggrid, 256, gsmem>>>(qsh, qsl, wqh, wql, bq, g1, be1, mm1, mv1, qh_p);
    gemm_kernel<true><<<ggrid, 256, gsmem>>>(ksh, ksl, wkh, wkl, bk, g2, be2, mm2, mv2, kh_p);
    gemm_kernel<true><<<ggrid, 256, gsmem>>>(vsh, vsl, wvh, wvl, bv, g3, be3, mm3, mv3, vh_p);

    const size_t asmem = (size_t)(QT * SC_STRIDE + QT * QS_STRIDE + SS + 128 * VV_STRIDE) * sizeof(float);
    cudaFuncSetAttribute(attn_kernel, cudaFuncAttributeMaxDynamicSharedMemorySize, (int)asmem);
    dim3 agrid(SS / QT, HH, BB);
    attn_kernel<<<agrid, ATT_THREADS, asmem>>>(mask, attnOut);

    split_kernel<<<n4 / 256, 256>>>(ctx_p, csh, csl, n4);
    gemm_kernel<false><<<ggrid, 256, gsmem>>>(csh, csl, woh, wol, bo, nullptr, nullptr, nullptr, nullptr, out);
}

// round 7
// speedup vs baseline: 2.7963x; 1.8653x over previous
#include <cuda_runtime.h>
#include <cuda_bf16.h>
#include <cstdint>
#include <math.h>

#define BB 8
#define SS 1024
#define DD 1024
#define HH 16
#define DEPTH 64
#define NROWS (BB*SS)

// ================= scratch (device globals: allocation-free rule) =================
__device__ float g_ctx[(size_t)NROWS*DD];

__device__ __nv_bfloat16 g_qs_h[(size_t)NROWS*DD], g_qs_l[(size_t)NROWS*DD];
__device__ __nv_bfloat16 g_ks_h[(size_t)NROWS*DD], g_ks_l[(size_t)NROWS*DD];
__device__ __nv_bfloat16 g_vs_h[(size_t)NROWS*DD], g_vs_l[(size_t)NROWS*DD];
__device__ __nv_bfloat16 g_cs_h[(size_t)NROWS*DD], g_cs_l[(size_t)NROWS*DD];
__device__ __nv_bfloat16 g_wqt_h[(size_t)DD*DD], g_wqt_l[(size_t)DD*DD];
__device__ __nv_bfloat16 g_wkt_h[(size_t)DD*DD], g_wkt_l[(size_t)DD*DD];
__device__ __nv_bfloat16 g_wvt_h[(size_t)DD*DD], g_wvt_l[(size_t)DD*DD];
__device__ __nv_bfloat16 g_wot_h[(size_t)DD*DD], g_wot_l[(size_t)DD*DD];

// post-projection Q/K/V in split-head layout [B,H,S,64], bf16 hi/lo
__device__ __nv_bfloat16 g_qhh[(size_t)BB*HH*SS*DEPTH], g_qhl[(size_t)BB*HH*SS*DEPTH];
__device__ __nv_bfloat16 g_khh[(size_t)BB*HH*SS*DEPTH], g_khl[(size_t)BB*HH*SS*DEPTH];
__device__ __nv_bfloat16 g_vhh[(size_t)BB*HH*SS*DEPTH], g_vhl[(size_t)BB*HH*SS*DEPTH];

// ================= warp-MMA helpers (PTX-portable, sm_80+) =================
__device__ __forceinline__ uint32_t smem_u32(const void* p){
    uint32_t a;
    asm("{ .reg .u64 t; cvta.to.shared.u64 t, %1; cvt.u32.u64 %0, t; }" : "=r"(a) : "l"(p));
    return a;
}
__device__ __forceinline__ void ldm4(uint32_t* r, uint32_t addr){
    asm volatile("ldmatrix.sync.aligned.m8n8.x4.shared.b16 {%0,%1,%2,%3}, [%4];"
        : "=r"(r[0]), "=r"(r[1]), "=r"(r[2]), "=r"(r[3]) : "r"(addr));
}
__device__ __forceinline__ void ldm2t(uint32_t* r, uint32_t addr){
    asm volatile("ldmatrix.sync.aligned.m8n8.x2.trans.shared.b16 {%0,%1}, [%2];"
        : "=r"(r[0]), "=r"(r[1]) : "r"(addr));
}
__device__ __forceinline__ void mma_bf16(float* d, const uint32_t* a, const uint32_t* b){
    asm volatile("mma.sync.aligned.m16n8k16.row.col.f32.bf16.bf16.f32 "
        "{%0,%1,%2,%3}, {%4,%5,%6,%7}, {%8,%9}, {%0,%1,%2,%3};"
        : "+f"(d[0]), "+f"(d[1]), "+f"(d[2]), "+f"(d[3])
        : "r"(a[0]), "r"(a[1]), "r"(a[2]), "r"(a[3]), "r"(b[0]), "r"(b[1]));
}
__device__ __forceinline__ void cp16(uint32_t saddr, const void* g){
    asm volatile("cp.async.cg.shared.global [%0], [%1], 16;" :: "r"(saddr), "l"(g));
}

// ================= split: fp32 -> (bf16 hi, bf16 lo) =================
__global__ void split_kernel(const float* __restrict__ x,
                             __nv_bfloat16* __restrict__ hi, __nv_bfloat16* __restrict__ lo, int n4)
{
    int i = blockIdx.x * blockDim.x + threadIdx.x;
    if (i >= n4) return;
    float4 v = *(const float4*)(x + (size_t)i * 4);
    __nv_bfloat16 h0 = __float2bfloat16(v.x), h1 = __float2bfloat16(v.y);
    __nv_bfloat16 h2 = __float2bfloat16(v.z), h3 = __float2bfloat16(v.w);
    __nv_bfloat16 l0 = __float2bfloat16(v.x - __bfloat162float(h0));
    __nv_bfloat16 l1 = __float2bfloat16(v.y - __bfloat162float(h1));
    __nv_bfloat16 l2 = __float2bfloat16(v.z - __bfloat162float(h2));
    __nv_bfloat16 l3 = __float2bfloat16(v.w - __bfloat162float(h3));
    __nv_bfloat162* hp = (__nv_bfloat162*)(hi + (size_t)i * 4);
    __nv_bfloat162* lp = (__nv_bfloat162*)(lo + (size_t)i * 4);
    hp[0] = __nv_bfloat162(h0, h1); hp[1] = __nv_bfloat162(h2, h3);
    lp[0] = __nv_bfloat162(l0, l1); lp[1] = __nv_bfloat162(l2, l3);
}

// ================= transpose + split for weights: W[k][n] -> Wt[n][k] =================
__global__ void tsplit_kernel(const float* __restrict__ W,
                              __nv_bfloat16* __restrict__ th, __nv_bfloat16* __restrict__ tl)
{
    __shared__ float t[32][33];
    const int x0 = blockIdx.x * 32, y0 = blockIdx.y * 32;
    for (int i = threadIdx.y; i < 32; i += 8)
        t[i][threadIdx.x] = W[(size_t)(y0 + i) * DD + x0 + threadIdx.x];
    __syncthreads();
    for (int i = threadIdx.y; i < 32; i += 8) {
        float v = t[threadIdx.x][i];
        __nv_bfloat16 h = __float2bfloat16(v);
        __nv_bfloat16 l = __float2bfloat16(v - __bfloat162float(h));
        size_t o = (size_t)(x0 + i) * DD + y0 + threadIdx.x;
        th[o] = h; tl[o] = l;
    }
}

// ================= bf16x3 GEMM via mma.sync, cp.async double-buffered =================
// MODE 0: plain fp32 out [r,D] (bias+relu).  MODE 1: bias+relu+BN, bf16 hi/lo split-head out.
#define NC 32
#define BK 32
#define TSTRIDE 40
#define TILE_BYT (128*TSTRIDE*2)
#define STAGE_BYT (4*TILE_BYT)

template<int MODE>
__global__ __launch_bounds__(256)
void gemm_kernel(const __nv_bfloat16* __restrict__ Ah, const __nv_bfloat16* __restrict__ Al,
                 const __nv_bfloat16* __restrict__ Bh, const __nv_bfloat16* __restrict__ Bl,
                 const float* __restrict__ bias,
                 const float* __restrict__ gg, const float* __restrict__ be,
                 const float* __restrict__ mm, const float* __restrict__ mv,
                 float* __restrict__ out,
                 __nv_bfloat16* __restrict__ outh, __nv_bfloat16* __restrict__ outl)
{
    extern __shared__ char dsm[];
    __shared__ float s_bias[128], s_scale[128], s_shift[128];

    const int tid = threadIdx.x, lane = tid & 31, wid = tid >> 5;
    const int row0 = blockIdx.y * 128, col0 = blockIdx.x * 128;
    const uint32_t smb = smem_u32(dsm);

    if (tid < 128) {
        int c = col0 + tid;
        s_bias[tid] = bias[c];
        if (MODE == 1) {
            float sc = gg[c] * rsqrtf(mv[c] + 1e-3f);
            s_scale[tid] = sc;
            s_shift[tid] = be[c] - mm[c] * sc;
        }
    }

    const __nv_bfloat16* srcs[4] = {Ah, Al, Bh, Bl};

    auto fill = [&](int c, int bsel) {
        const int k0 = c * BK;
        #pragma unroll
        for (int t = 0; t < 4; t++) {
            const __nv_bfloat16* src = srcs[t];
            const int rbase = (t >= 2) ? col0 : row0;
            #pragma unroll
            for (int i = 0; i < 2; i++) {
                int idx = tid + i * 256;
                int r = idx >> 2, c4 = idx & 3;
                uint32_t sa = smb + bsel * STAGE_BYT + t * TILE_BYT + (r * TSTRIDE + c4 * 8) * 2;
                cp16(sa, src + (size_t)(rbase + r) * DD + k0 + c4 * 8);
            }
        }
        asm volatile("cp.async.commit_group;");
    };

    const int wm = (wid & 3) * 32, wn = (wid >> 2) * 64;
    const int aRow = wm + (lane & 15);
    const int aK   = (lane >> 4) * 8;
    const int bRow = wn + (lane & 7) + ((lane >> 4) << 3);
    const int bK   = ((lane >> 3) & 1) * 8;

    float acc[2][8][4];
    #pragma unroll
    for (int m = 0; m < 2; m++)
        #pragma unroll
        for (int n = 0; n < 8; n++)
            #pragma unroll
            for (int u = 0; u < 4; u++) acc[m][n][u] = 0.f;

    auto compute = [&](int bsel) {
        const uint32_t stg = smb + bsel * STAGE_BYT;
        #pragma unroll
        for (int kk = 0; kk < BK; kk += 16) {
            uint32_t ahf[2][4], alf[2][4];
            #pragma unroll
            for (int m = 0; m < 2; m++) {
                const uint32_t off = ((aRow + m * 16) * TSTRIDE + kk + aK) * 2;
                ldm4(ahf[m], stg + off);
                ldm4(alf[m], stg + TILE_BYT + off);
            }
            #pragma unroll
            for (int g = 0; g < 4; g++) {
                const uint32_t off = ((bRow + g * 16) * TSTRIDE + kk + bK) * 2;
                uint32_t bh2[4], bl2[4];
                ldm4(bh2, stg + 2 * TILE_BYT + off);
                ldm4(bl2, stg + 3 * TILE_BYT + off);
                #pragma unroll
                for (int m = 0; m < 2; m++) {
                    mma_bf16(acc[m][2*g],   ahf[m], bh2);
                    mma_bf16(acc[m][2*g],   ahf[m], bl2);
                    mma_bf16(acc[m][2*g],   alf[m], bh2);
                    mma_bf16(acc[m][2*g+1], ahf[m], bh2 + 2);
                    mma_bf16(acc[m][2*g+1], ahf[m], bl2 + 2);
                    mma_bf16(acc[m][2*g+1], alf[m], bh2 + 2);
                }
            }
        }
    };

    fill(0, 0);
    for (int c = 0; c < NC; c++) {
        if (c + 1 < NC) {
            fill(c + 1, (c + 1) & 1);
            asm volatile("cp.async.wait_group 1;" ::: "memory");
        } else {
            asm volatile("cp.async.wait_group 0;" ::: "memory");
        }
        __syncthreads();
        compute(c & 1);
        __syncthreads();
    }

    #pragma unroll
    for (int m = 0; m < 2; m++) {
        #pragma unroll
        for (int h2 = 0; h2 < 2; h2++) {
            const int r = row0 + wm + m * 16 + h2 * 8 + (lane >> 2);
            const int bidx = r >> 10, sidx = r & 1023;
            #pragma unroll
            for (int n = 0; n < 8; n++) {
                const int cl = wn + n * 8 + (lane & 3) * 2;
                float v0 = acc[m][n][h2 ? 2 : 0];
                float v1 = acc[m][n][h2 ? 3 : 1];
                v0 = fmaxf(v0 + s_bias[cl],     0.f);
                v1 = fmaxf(v1 + s_bias[cl + 1], 0.f);
                if (MODE == 1) {
                    v0 = v0 * s_scale[cl]     + s_shift[cl];
                    v1 = v1 * s_scale[cl + 1] + s_shift[cl + 1];
                    const int cg = col0 + cl;
                    const int hh = cg >> 6, d0i = cg & 63;
                    const size_t idx = (((size_t)bidx * HH + hh) * SS + sidx) * DEPTH + d0i;
                    __nv_bfloat16 h0 = __float2bfloat16(v0);
                    __nv_bfloat16 h1 = __float2bfloat16(v1);
                    __nv_bfloat16 l0 = __float2bfloat16(v0 - __bfloat162float(h0));
                    __nv_bfloat16 l1 = __float2bfloat16(v1 - __bfloat162float(h1));
                    *(__nv_bfloat162*)&outh[idx] = __nv_bfloat162(h0, h1);
                    *(__nv_bfloat162*)&outl[idx] = __nv_bfloat162(l0, l1);
                } else {
                    float2 p; p.x = v0; p.y = v1;
                    *(float2*)&out[(size_t)r * DD + col0 + cl] = p;
                }
            }
        }
    }
}

// ================= tensorized attention =================
// 32 q-rows per CTA, 256 threads (8 warps). Phase1: QK^T bf16x3 mma. Phase2: softmax,
// P stored bf16 hi/lo in-place over score rows. Phase3: P@V bf16x3 mma (V via ldmatrix.trans).
#define SC_ROWB 4112            // bytes per score row (1028 floats); 16B aligned, conflict-free
#define OFF_Q   131584
#define QL_OFF  4608
#define OFF_KV  140800
#define KV_STAGE_B 36864
#define KV_L_OFF   18432
#define OFF_MROW 214528
#define ATT_SMEM 218624

__global__ __launch_bounds__(256, 1)
void attn_kernel(const float* __restrict__ mask, float* __restrict__ attnOut)
{
    extern __shared__ char smc[];
    const uint32_t smb = smem_u32(smc);
    float* sc   = (float*)smc;                       // row r at float offset r*1028
    float* mrow = (float*)(smc + OFF_MROW);

    const int tid = threadIdx.x, lane = tid & 31, warp = tid >> 5;
    const int qt0 = blockIdx.x * 32;
    const int h = blockIdx.y, b = blockIdx.z;
    const size_t bh = (size_t)b * HH + h;
    const __nv_bfloat16 *qhhp = g_qhh + bh * SS * DEPTH, *qhlp = g_qhl + bh * SS * DEPTH;
    const __nv_bfloat16 *khhp = g_khh + bh * SS * DEPTH, *khlp = g_khl + bh * SS * DEPTH;
    const __nv_bfloat16 *vhhp = g_vhh + bh * SS * DEPTH, *vhlp = g_vhl + bh * SS * DEPTH;

    // mask premultiplied by -1e9
    {
        float4 v = *(const float4*)&mask[(size_t)b * SS + tid * 4];
        v.x *= -1e9f; v.y *= -1e9f; v.z *= -1e9f; v.w *= -1e9f;
        *(float4*)&mrow[tid * 4] = v;
    }

    // Q tile (hi/lo) -> smem via cp.async
    #pragma unroll
    for (int t = 0; t < 2; t++) {
        int idx = tid + t * 256;                 // 0..511
        const __nv_bfloat16* src = (idx < 256) ? qhhp : qhlp;
        int i2 = idx & 255; int r = i2 >> 3, c = i2 & 7;
        uint32_t dst = smb + OFF_Q + ((idx < 256) ? 0 : QL_OFF) + r * 144 + c * 16;
        cp16(dst, src + (size_t)(qt0 + r) * DEPTH + c * 8);
    }
    asm volatile("cp.async.commit_group;");

    auto fillKV = [&](const __nv_bfloat16* sh, const __nv_bfloat16* sl, int j0, int stage){
        #pragma unroll
        for (int t = 0; t < 8; t++) {
            int idx = tid + t * 256;             // 0..2047
            int hl = idx >> 10;
            int i2 = idx & 1023; int r = i2 >> 3, c = i2 & 7;
            uint32_t dst = smb + OFF_KV + stage * KV_STAGE_B + hl * KV_L_OFF + r * 144 + c * 16;
            const __nv_bfloat16* src = hl ? sl : sh;
            cp16(dst, src + (size_t)(j0 + r) * DEPTH + c * 8);
        }
        asm volatile("cp.async.commit_group;");
    };

    fillKV(khhp, khlp, 0, 0);
    asm volatile("cp.async.wait_group 0;" ::: "memory");
    __syncthreads();

    // A fragments (Q) once into registers: 4 ksteps x 2 m-atoms x hi/lo
    uint32_t aqh[4][2][4], aql[4][2][4];
    {
        const int aRow = lane & 15, aKs = (lane >> 4) * 8;
        #pragma unroll
        for (int ks = 0; ks < 4; ks++)
            #pragma unroll
            for (int m = 0; m < 2; m++) {
                uint32_t off = smb + OFF_Q + (m * 16 + aRow) * 144 + (ks * 16 + aKs) * 2;
                ldm4(aqh[ks][m], off);
                ldm4(aql[ks][m], off + QL_OFF);
            }
    }

    // ---- Phase 1: scores ----
    const int bRow = warp * 16 + (lane & 7) + ((lane >> 4) << 3);
    const int bKs  = ((lane >> 3) & 1) * 8;
    for (int jc = 0; jc < 8; jc++) {
        if (jc + 1 < 8) {
            fillKV(khhp, khlp, (jc + 1) * 128, (jc + 1) & 1);
            asm volatile("cp.async.wait_group 1;" ::: "memory");
        } else {
            asm volatile("cp.async.wait_group 0;" ::: "memory");
        }
        __syncthreads();
        const uint32_t base = smb + OFF_KV + (jc & 1) * KV_STAGE_B;
        float acc[2][2][4];
        #pragma unroll
        for (int m = 0; m < 2; m++)
            #pragma unroll
            for (int na = 0; na < 2; na++)
                #pragma unroll
                for (int u = 0; u < 4; u++) acc[m][na][u] = 0.f;

        #pragma unroll
        for (int ks = 0; ks < 4; ks++) {
            uint32_t bh4[4], bl4[4];
            uint32_t off = base + bRow * 144 + (ks * 16 + bKs) * 2;
            ldm4(bh4, off);
            ldm4(bl4, off + KV_L_OFF);
            #pragma unroll
            for (int m = 0; m < 2; m++) {
                mma_bf16(acc[m][0], aqh[ks][m], bh4);
                mma_bf16(acc[m][0], aqh[ks][m], bl4);
                mma_bf16(acc[m][0], aql[ks][m], bh4);
                mma_bf16(acc[m][1], aqh[ks][m], bh4 + 2);
                mma_bf16(acc[m][1], aqh[ks][m], bl4 + 2);
                mma_bf16(acc[m][1], aql[ks][m], bh4 + 2);
            }
        }
        #pragma unroll
        for (int m = 0; m < 2; m++)
            #pragma unroll
            for (int na = 0; na < 2; na++) {
                const int col = jc * 128 + warp * 16 + na * 8 + (lane & 3) * 2;
                const float m0 = mrow[col], m1 = mrow[col + 1];
                const int r0i = m * 16 + (lane >> 2);
                float2 p0; p0.x = acc[m][na][0] * 0.125f + m0; p0.y = acc[m][na][1] * 0.125f + m1;
                *(float2*)&sc[r0i * 1028 + col] = p0;
                float2 p1; p1.x = acc[m][na][2] * 0.125f + m0; p1.y = acc[m][na][3] * 0.125f + m1;
                *(float2*)&sc[(r0i + 8) * 1028 + col] = p1;
            }
        __syncthreads();
    }

    // ---- Phase 2: softmax; write attn fp32 to gmem; store P bf16 hi/lo in-place ----
    for (int rr = 0; rr < 4; rr++) {
        const int r = warp * 4 + rr;
        float* row = sc + r * 1028;
        float x[32];
        float mx = -3.4e38f;
        #pragma unroll
        for (int t = 0; t < 32; t++) { x[t] = row[lane + 32 * t]; mx = fmaxf(mx, x[t]); }
        #pragma unroll
        for (int o = 16; o > 0; o >>= 1) mx = fmaxf(mx, __shfl_xor_sync(0xffffffffu, mx, o));
        float sum = 0.f;
        #pragma unroll
        for (int t = 0; t < 32; t++) { x[t] = __expf(x[t] - mx); sum += x[t]; }
        #pragma unroll
        for (int o = 16; o > 0; o >>= 1) sum += __shfl_xor_sync(0xffffffffu, sum, o);
        const float inv = 1.f / sum;
        float* gout = attnOut + (bh * SS + qt0 + r) * SS;
        __nv_bfloat16* ph = (__nv_bfloat16*)((char*)row);
        __nv_bfloat16* pl = (__nv_bfloat16*)((char*)row + 2048);
        #pragma unroll
        for (int t = 0; t < 32; t++) {
            const int j = lane + 32 * t;
            const float p = x[t] * inv;
            gout[j] = p;
            __nv_bfloat16 hb = __float2bfloat16(p);
            ph[j] = hb;
            pl[j] = __float2bfloat16(p - __bfloat162float(hb));
        }
    }
    // prefetch V chunk 0 (stage0 free; softmax doesn't touch KV region)
    fillKV(vhhp, vhlp, 0, 0);
    __syncthreads();

    // ---- Phase 3: ctx = P @ V ----
    float facc[2][4];
    #pragma unroll
    for (int m = 0; m < 2; m++)
        #pragma unroll
        for (int u = 0; u < 4; u++) facc[m][u] = 0.f;

    for (int jc = 0; jc < 8; jc++) {
        if (jc + 1 < 8) {
            fillKV(vhhp, vhlp, (jc + 1) * 128, (jc + 1) & 1);
            asm volatile("cp.async.wait_group 1;" ::: "memory");
        } else {
            asm volatile("cp.async.wait_group 0;" ::: "memory");
        }
        __syncthreads();
        const uint32_t vbase = smb + OFF_KV + (jc & 1) * KV_STAGE_B;
        #pragma unroll
        for (int ks = 0; ks < 8; ks++) {
            const int jcol = jc * 128 + ks * 16;
            uint32_t ah[2][4], al2[2][4];
            #pragma unroll
            for (int m = 0; m < 2; m++) {
                uint32_t off = smb + (m * 16 + (lane & 15)) * SC_ROWB + (jcol + (lane >> 4) * 8) * 2;
                ldm4(ah[m], off);
                ldm4(al2[m], off + 2048);
            }
            uint32_t bvh[2], bvl[2];
            uint32_t voff = vbase + (ks * 16 + (lane & 15)) * 144 + warp * 16;
            ldm2t(bvh, voff);
            ldm2t(bvl, voff + KV_L_OFF);
            #pragma unroll
            for (int m = 0; m < 2; m++) {
                mma_bf16(facc[m], ah[m], bvh);
                mma_bf16(facc[m], ah[m], bvl);
                mma_bf16(facc[m], al2[m], bvh);
            }
        }
        __syncthreads();
    }

    // write ctx [b, s, h*64 + d]
    {
        const int col = h * DEPTH + warp * 8 + (lane & 3) * 2;
        #pragma unroll
        for (int m = 0; m < 2; m++) {
            const int rg = qt0 + m * 16 + (lane >> 2);
            *(float2*)&g_ctx[((size_t)b * SS + rg) * DD + col]     = make_float2(facc[m][0], facc[m][1]);
            *(float2*)&g_ctx[((size_t)b * SS + rg + 8) * DD + col] = make_float2(facc[m][2], facc[m][3]);
        }
    }
}

// ================= launch =================
extern "C" void kernel_launch(void* const* d_in, const int* in_sizes, int n_in,
                              void* d_out, int out_size)
{
    const float* q    = (const float*)d_in[0];
    const float* k    = (const float*)d_in[1];
    const float* v    = (const float*)d_in[2];
    const float* mask = (const float*)d_in[3];
    const float* wq = (const float*)d_in[4];   const float* bq = (const float*)d_in[5];
    const float* wk = (const float*)d_in[6];   const float* bk = (const float*)d_in[7];
    const float* wv = (const float*)d_in[8];   const float* bv = (const float*)d_in[9];
    const float* wo = (const float*)d_in[10];  const float* bo = (const float*)d_in[11];
    const float* g1 = (const float*)d_in[12];  const float* be1 = (const float*)d_in[13];
    const float* mm1= (const float*)d_in[14];  const float* mv1 = (const float*)d_in[15];
    const float* g2 = (const float*)d_in[16];  const float* be2 = (const float*)d_in[17];
    const float* mm2= (const float*)d_in[18];  const float* mv2 = (const float*)d_in[19];
    const float* g3 = (const float*)d_in[20];  const float* be3 = (const float*)d_in[21];
    const float* mm3= (const float*)d_in[22];  const float* mv3 = (const float*)d_in[23];

    float* out = (float*)d_out;                   // [B,S,D] first (tuple order)
    float* attnOut = out + (size_t)NROWS * DD;    // then [B,H,S,S]

    float *ctx_p;
    cudaGetSymbolAddress((void**)&ctx_p, g_ctx);
    __nv_bfloat16 *qsh, *qsl, *ksh, *ksl, *vsh, *vsl, *csh, *csl;
    __nv_bfloat16 *wqh, *wql, *wkh, *wkl, *wvh, *wvl, *woh, *wol;
    __nv_bfloat16 *qhh, *qhl, *khh, *khl, *vhh, *vhl;
    cudaGetSymbolAddress((void**)&qsh, g_qs_h); cudaGetSymbolAddress((void**)&qsl, g_qs_l);
    cudaGetSymbolAddress((void**)&ksh, g_ks_h); cudaGetSymbolAddress((void**)&ksl, g_ks_l);
    cudaGetSymbolAddress((void**)&vsh, g_vs_h); cudaGetSymbolAddress((void**)&vsl, g_vs_l);
    cudaGetSymbolAddress((void**)&csh, g_cs_h); cudaGetSymbolAddress((void**)&csl, g_cs_l);
    cudaGetSymbolAddress((void**)&wqh, g_wqt_h); cudaGetSymbolAddress((void**)&wql, g_wqt_l);
    cudaGetSymbolAddress((void**)&wkh, g_wkt_h); cudaGetSymbolAddress((void**)&wkl, g_wkt_l);
    cudaGetSymbolAddress((void**)&wvh, g_wvt_h); cudaGetSymbolAddress((void**)&wvl, g_wvt_l);
    cudaGetSymbolAddress((void**)&woh, g_wot_h); cudaGetSymbolAddress((void**)&wol, g_wot_l);
    cudaGetSymbolAddress((void**)&qhh, g_qhh); cudaGetSymbolAddress((void**)&qhl, g_qhl);
    cudaGetSymbolAddress((void**)&khh, g_khh); cudaGetSymbolAddress((void**)&khl, g_khl);
    cudaGetSymbolAddress((void**)&vhh, g_vhh); cudaGetSymbolAddress((void**)&vhl, g_vhl);

    const int n4 = NROWS * DD / 4;
    split_kernel<<<n4 / 256, 256>>>(q, qsh, qsl, n4);
    split_kernel<<<n4 / 256, 256>>>(k, ksh, ksl, n4);
    split_kernel<<<n4 / 256, 256>>>(v, vsh, vsl, n4);
    dim3 tgrid(DD / 32, DD / 32), tblk(32, 8);
    tsplit_kernel<<<tgrid, tblk>>>(wq, wqh, wql);
    tsplit_kernel<<<tgrid, tblk>>>(wk, wkh, wkl);
    tsplit_kernel<<<tgrid, tblk>>>(wv, wvh, wvl);
    tsplit_kernel<<<tgrid, tblk>>>(wo, woh, wol);

    const int gsmem = 2 * STAGE_BYT;   // 81920
    cudaFuncSetAttribute(gemm_kernel<0>, cudaFuncAttributeMaxDynamicSharedMemorySize, gsmem);
    cudaFuncSetAttribute(gemm_kernel<1>, cudaFuncAttributeMaxDynamicSharedMemorySize, gsmem);
    dim3 ggrid(DD / 128, NROWS / 128);
    gemm_kernel<1><<<ggrid, 256, gsmem>>>(qsh, qsl, wqh, wql, bq, g1, be1, mm1, mv1, nullptr, qhh, qhl);
    gemm_kernel<1><<<ggrid, 256, gsmem>>>(ksh, ksl, wkh, wkl, bk, g2, be2, mm2, mv2, nullptr, khh, khl);
    gemm_kernel<1><<<ggrid, 256, gsmem>>>(vsh, vsl, wvh, wvl, bv, g3, be3, mm3, mv3, nullptr, vhh, vhl);

    cudaFuncSetAttribute(attn_kernel, cudaFuncAttributeMaxDynamicSharedMemorySize, ATT_SMEM);
    dim3 agrid(SS / 32, HH, BB);
    attn_kernel<<<agrid, 256, ATT_SMEM>>>(mask, attnOut);

    split_kernel<<<n4 / 256, 256>>>(ctx_p, csh, csl, n4);
    gemm_kernel<0><<<ggrid, 256, gsmem>>>(csh, csl, woh, wol, bo, nullptr, nullptr, nullptr, nullptr, out, nullptr, nullptr);
}